// round 6
// baseline (speedup 1.0000x reference)
#include <cuda_runtime.h>

// SimplePatchScorer: out[b, j] = dot(W, permuted_patch_row(b, j)) + bias
//   x: (512, 3, 224, 224) fp32, W: (1,768), b: (1,) -> out: (512, 196)
//
// flat[u], u = s*588 + v; s = ph*16+pw; v = c*196 + hn*14 + wn.
// out[b,j] = sum_t W[t]*flat[768j+t] + bias.
// lcm(588,768)=37632 => 4 groups/image: s in [64g,64g+64), j in [49g,49g+49).
//
// v4: 256-thread CTAs, QUARTER tiles (16 s' rows = one ph value, 37.7 KB)
// -> ~40 KB smem, 5 CTAs/SM, 62.5% occ. Phase-2 uses incremental (sp,v)
// tracking (no per-element div); phase-1 uses carry-chain index decode.
// 7 register accumulators per warp persist across the 4 quarter-phases.

#define VPAD      589          // 588 + 1 (row-cross bump = +33)
#define QUARTER_U 9408         // 16 * 588
#define THREADS   256

__global__ __launch_bounds__(THREADS, 5)
void patch_scorer_v4(const float* __restrict__ x,
                     const float* __restrict__ W,
                     const float* __restrict__ bias,
                     float* __restrict__ out)
{
    extern __shared__ float smem[];
    float* Y  = smem;               // [16][589]
    float* Ws = smem + 16 * VPAD;   // [768]

    const int tid  = threadIdx.x;
    const int g    = blockIdx.x & 3;
    const int b    = blockIdx.x >> 2;
    const int lane = tid & 31;
    const int warp = tid >> 5;      // 8 warps

    const float* xb = x + (size_t)b * (3 * 224 * 224);

    if (tid < 192)                  // 192 * float4 = 768 floats
        ((float4*)Ws)[tid] = ((const float4*)W)[tid];
    // covered by the __syncthreads() before the first phase-2 read

    float acc[7];
    #pragma unroll
    for (int i = 0; i < 7; i++) acc[i] = 0.f;

    #pragma unroll
    for (int q = 0; q < 4; q++) {
        if (q) __syncthreads();     // protect Y before overwrite

        // ---- Phase 1: stream quarter's region -> smem tile (coalesced) ----
        // ph = 4g + q; region: c in [0,3), hn in [0,14), w in [0,224)
        // 42 image rows x 56 float4 = 2352 float4 over 256 threads.
        {
            const int hoff = 4 * g + q;           // ph
            int w4 = tid % 56;                    // float4 col
            int r  = tid / 56;                    // row index (c*14 + hn)
            int hn = r % 14;
            int c  = r / 14;
            for (int e4 = tid; e4 < 2352; e4 += THREADS) {
                int w = w4 << 2;
                float4 val = *(const float4*)(xb +
                    (size_t)c * 50176 + (hn * 16 + hoff) * 224 + w);

                int pw = w & 15;                  // 0,4,8,12
                int wn = w >> 4;
                float* dst = &Y[pw * VPAD + c * 196 + hn * 14 + wn];
                dst[0 * VPAD] = val.x;
                dst[1 * VPAD] = val.y;
                dst[2 * VPAD] = val.z;
                dst[3 * VPAD] = val.w;

                // carry-chain advance: e4 += 256 => w4 += 32 (mod 56), r += 4/5
                w4 += 32;
                int rinc = 4;
                if (w4 >= 56) { w4 -= 56; rinc = 5; }
                hn += rinc;
                if (hn >= 14) { hn -= 14; c++; }
            }
        }
        __syncthreads();

        // ---- Phase 2: dot segments inside this quarter's u' range ----
        const int rlo = QUARTER_U * q, rhi = rlo + QUARTER_U;
        const int spoff = 16 * q;

        #pragma unroll
        for (int i = 0; i < 7; i++) {
            int jl = warp + 8 * i;                // warp owns jl = warp (mod 8)
            if (jl < 49) {
                int ulo = max(768 * jl, rlo);
                int uhi = min(768 * jl + 768, rhi);
                int u   = ulo + lane;
                if (u < uhi) {
                    int sp = (unsigned)u / 588u;  // one div per segment
                    int v  = u - sp * 588;
                    const float* yp = &Y[(sp - spoff) * VPAD + v];
                    const float* wp = &Ws[u - 768 * jl];
                    float a = 0.f;
                    while (u < uhi) {
                        a += wp[0] * yp[0];
                        wp += 32;
                        u  += 32;
                        v  += 32;
                        if (v >= 588) { v -= 588; yp += 33; }
                        else          {           yp += 32; }
                    }
                    acc[i] += a;
                }
            }
        }
    }

    // ---- final warp reductions + store ----
    const float bv = __ldg(bias);
    #pragma unroll
    for (int i = 0; i < 7; i++) {
        int jl = warp + 8 * i;
        if (jl < 49) {
            float a = acc[i];
            #pragma unroll
            for (int off = 16; off; off >>= 1)
                a += __shfl_xor_sync(0xffffffffu, a, off);
            if (lane == 0)
                out[b * 196 + 49 * g + jl] = a + bv;
        }
    }
}

extern "C" void kernel_launch(void* const* d_in, const int* in_sizes, int n_in,
                              void* d_out, int out_size)
{
    const float* x  = (const float*)d_in[0];
    const float* W  = (const float*)d_in[1];
    const float* bb = (const float*)d_in[2];
    float* out = (float*)d_out;

    const int smem_bytes = (16 * VPAD + 768) * sizeof(float);  // ~40.8 KB
    cudaFuncSetAttribute(patch_scorer_v4,
                         cudaFuncAttributeMaxDynamicSharedMemorySize, smem_bytes);

    patch_scorer_v4<<<512 * 4, THREADS, smem_bytes>>>(x, W, bb, out);
}

// round 7
// speedup vs baseline: 1.2987x; 1.2987x over previous
#include <cuda_runtime.h>

// SimplePatchScorer: out[b, j] = dot(W, permuted_patch_row(b, j)) + bias
//   x: (512, 3, 224, 224) fp32, W: (1,768), b: (1,) -> out: (512, 196)
//
// flat[u], u = s*588 + v; s = ph*16+pw; v = c*196 + hn*14 + wn.
// out[b,j] = sum_t W[t]*flat[768j+t] + bias.
// lcm(588,768)=37632 => 4 groups/image: s in [64g,64g+64), j in [49g,49g+49).
//
// v5: 256-thread CTAs, quarter tiles (16 s' rows = one ph). VPAD=604
// (mult of 4) => phase-2 uses conflict-free float4 LDS for BOTH Y and W
// (segment starts are 0 mod 4; row boundary 588 is 0 mod 4, so a float4
// never straddles an s' row). Phase-1 stores are <=2-way conflicted.
// ~40.8 KB smem -> 5 CTAs/SM. 7 register accumulators persist.

#define VPAD      604
#define QUARTER_U 9408         // 16 * 588
#define THREADS   256

__global__ __launch_bounds__(THREADS, 5)
void patch_scorer_v5(const float* __restrict__ x,
                     const float* __restrict__ W,
                     const float* __restrict__ bias,
                     float* __restrict__ out)
{
    extern __shared__ float smem[];
    float* Y  = smem;               // [16][604]
    float* Ws = smem + 16 * VPAD;   // [768]

    const int tid  = threadIdx.x;
    const int g    = blockIdx.x & 3;
    const int b    = blockIdx.x >> 2;
    const int lane = tid & 31;
    const int warp = tid >> 5;      // 8 warps

    const float* xb = x + (size_t)b * (3 * 224 * 224);

    if (tid < 192)                  // 192 float4 = 768 floats
        ((float4*)Ws)[tid] = ((const float4*)W)[tid];
    // covered by the __syncthreads() before the first phase-2 read

    float acc[7];
    #pragma unroll
    for (int i = 0; i < 7; i++) acc[i] = 0.f;

    #pragma unroll
    for (int q = 0; q < 4; q++) {
        if (q) __syncthreads();     // protect Y before overwrite

        // ---- Phase 1: stream quarter's region -> smem tile (coalesced) ----
        // ph = 4g + q; region: c in [0,3), hn in [0,14), w in [0,224)
        // 42 image rows x 56 float4 = 2352 float4 over 256 threads.
        {
            const int hoff = 4 * g + q;           // ph
            int w4 = tid % 56;                    // float4 col
            int r  = tid / 56;                    // row index (c*14 + hn)
            int hn = r % 14;
            int c  = r / 14;
            #pragma unroll 2
            for (int e4 = tid; e4 < 2352; e4 += THREADS) {
                int w = w4 << 2;
                float4 val = __ldcs((const float4*)(xb +
                    (size_t)c * 50176 + (hn * 16 + hoff) * 224 + w));

                int pw = w & 15;                  // 0,4,8,12
                int wn = w >> 4;
                float* dst = &Y[pw * VPAD + c * 196 + hn * 14 + wn];
                dst[0 * VPAD] = val.x;
                dst[1 * VPAD] = val.y;
                dst[2 * VPAD] = val.z;
                dst[3 * VPAD] = val.w;

                // carry-chain advance: e4 += 256 => w4 += 32 (mod 56), r += 4/5
                w4 += 32;
                int rinc = 4;
                if (w4 >= 56) { w4 -= 56; rinc = 5; }
                hn += rinc;
                if (hn >= 14) { hn -= 14; c++; }
            }
        }
        __syncthreads();

        // ---- Phase 2: vectorized dot over this quarter's u' range ----
        const int rlo = QUARTER_U * q, rhi = rlo + QUARTER_U;
        const int spoff = 16 * q;

        #pragma unroll
        for (int i = 0; i < 7; i++) {
            int jl = warp + 8 * i;                // warp owns jl = warp (mod 8)
            if (jl < 49) {
                int ulo = max(768 * jl, rlo);
                int uhi = min(768 * jl + 768, rhi);
                int u   = ulo + 4 * lane;         // lane's first float4
                if (u < uhi) {
                    int sp = (unsigned)u / 588u;  // one div per segment
                    int v  = u - sp * 588;
                    int yo = (sp - spoff) * VPAD + v;   // float index into Y
                    int wo = u - 768 * jl;              // float index into Ws
                    float a = 0.f;
                    #pragma unroll 2
                    while (u < uhi) {
                        float4 yv = *(const float4*)&Y[yo];
                        float4 wv = *(const float4*)&Ws[wo];
                        a = fmaf(wv.x, yv.x, a);
                        a = fmaf(wv.y, yv.y, a);
                        a = fmaf(wv.z, yv.z, a);
                        a = fmaf(wv.w, yv.w, a);
                        u  += 128;                // 32 lanes * 4 floats
                        wo += 128;
                        v  += 128;
                        yo += 128;
                        if (v >= 588) { v -= 588; yo += VPAD - 588; }
                    }
                    acc[i] += a;
                }
            }
        }
    }

    // ---- final warp reductions + store ----
    const float bv = __ldg(bias);
    #pragma unroll
    for (int i = 0; i < 7; i++) {
        int jl = warp + 8 * i;
        if (jl < 49) {
            float a = acc[i];
            #pragma unroll
            for (int off = 16; off; off >>= 1)
                a += __shfl_xor_sync(0xffffffffu, a, off);
            if (lane == 0)
                out[b * 196 + 49 * g + jl] = a + bv;
        }
    }
}

extern "C" void kernel_launch(void* const* d_in, const int* in_sizes, int n_in,
                              void* d_out, int out_size)
{
    const float* x  = (const float*)d_in[0];
    const float* W  = (const float*)d_in[1];
    const float* bb = (const float*)d_in[2];
    float* out = (float*)d_out;

    const int smem_bytes = (16 * VPAD + 768) * sizeof(float);  // ~40.8 KB
    cudaFuncSetAttribute(patch_scorer_v5,
                         cudaFuncAttributeMaxDynamicSharedMemorySize, smem_bytes);

    patch_scorer_v5<<<512 * 4, THREADS, smem_bytes>>>(x, W, bb, out);
}